// round 10
// baseline (speedup 1.0000x reference)
#include <cuda_runtime.h>
#include <cuda_fp16.h>
#include <cstdint>

#define D 64
#define MAX_NODES 50000
#define CAP 128            // bucket capacity per node (Poisson(16) degrees)
#define OVF_CAP 4096

// ---- scratch ----
__device__ __half g_support_h[MAX_NODES * D];       // X @ W in fp16 (6.4 MB)
__device__ int    g_cnt[MAX_NODES + 1];             // per-dst counters; [MAX_NODES] = novf
__device__ int2   g_bucket[MAX_NODES * CAP];        // (src, bitcast(w)) per dst (51.2 MB)
__device__ int3   g_ovf[OVF_CAP];                   // (dst, src, w) spill

// ---------------------------------------------------------------------------
// single-pass bucket fill
// ---------------------------------------------------------------------------
__global__ void fill_kernel(const int* __restrict__ edge_src,
                            const int* __restrict__ edge_dst,
                            const float* __restrict__ edge_weight, int n_edges) {
    int e = blockIdx.x * blockDim.x + threadIdx.x;
    if (e >= n_edges) return;
    int d = edge_dst[e];
    int slot = atomicAdd(&g_cnt[d], 1);
    if (slot < CAP) {
        g_bucket[d * CAP + slot] = make_int2(edge_src[e], __float_as_int(edge_weight[e]));
    } else {
        int o = atomicAdd(&g_cnt[MAX_NODES], 1);
        if (o < OVF_CAP)
            g_ovf[o] = make_int3(d, edge_src[e], __float_as_int(edge_weight[e]));
    }
}

// ---------------------------------------------------------------------------
// tensor-core GEMM: support_h = fp16( X @ W ), fp32 accumulate.
// Block = 64 rows x 64 cols, 128 threads (4 warps), warp = 16-row strip.
// 782 blocks -> ~5.3 blocks/SM for DRAM-load concurrency.
// ---------------------------------------------------------------------------
#define GR 64
#define LDA 72   // padded leading dim in halves (144B rows -> conflict-free ldmatrix)

__device__ __forceinline__ uint32_t smem_u32(const void* p) {
    return static_cast<uint32_t>(__cvta_generic_to_shared(p));
}

__device__ __forceinline__ void ldsm_x4(uint32_t& r0, uint32_t& r1,
                                        uint32_t& r2, uint32_t& r3, uint32_t addr) {
    asm volatile("ldmatrix.sync.aligned.m8n8.x4.shared.b16 {%0,%1,%2,%3}, [%4];"
                 : "=r"(r0), "=r"(r1), "=r"(r2), "=r"(r3) : "r"(addr));
}

__device__ __forceinline__ void ldsm_x2_trans(uint32_t& r0, uint32_t& r1, uint32_t addr) {
    asm volatile("ldmatrix.sync.aligned.m8n8.x2.trans.shared.b16 {%0,%1}, [%2];"
                 : "=r"(r0), "=r"(r1) : "r"(addr));
}

__device__ __forceinline__ void mma_16816(float* c, uint32_t a0, uint32_t a1,
                                          uint32_t a2, uint32_t a3,
                                          uint32_t b0, uint32_t b1) {
    asm volatile(
        "mma.sync.aligned.m16n8k16.row.col.f32.f16.f16.f32 "
        "{%0,%1,%2,%3}, {%4,%5,%6,%7}, {%8,%9}, {%0,%1,%2,%3};"
        : "+f"(c[0]), "+f"(c[1]), "+f"(c[2]), "+f"(c[3])
        : "r"(a0), "r"(a1), "r"(a2), "r"(a3), "r"(b0), "r"(b1));
}

__global__ __launch_bounds__(128) void gcn_gemm_hmma(
    const float* __restrict__ X, const float* __restrict__ W, int n_nodes) {
    __shared__ __align__(16) __half sA[GR][LDA];  // X tile fp16 (9.2 KB)
    __shared__ __align__(16) __half sB[D][LDA];   // W fp16      (9.2 KB)

    const int tid = threadIdx.x;
    const int lane = tid & 31;
    const int warp = tid >> 5;
    const int row0 = blockIdx.x * GR;

    // load + convert W (64x64): thread t -> row t>>1, half (t&1)*32
    {
        const int r = tid >> 1;
        const int c0 = (tid & 1) * 32;
#pragma unroll
        for (int j = 0; j < 8; j++) {
            float4 v = *reinterpret_cast<const float4*>(W + r * D + c0 + j * 4);
            *reinterpret_cast<__half2*>(&sB[r][c0 + j * 4])     = __floats2half2_rn(v.x, v.y);
            *reinterpret_cast<__half2*>(&sB[r][c0 + j * 4 + 2]) = __floats2half2_rn(v.z, v.w);
        }
    }
    // load + convert X tile (64x64): same pattern
    {
        const int r = tid >> 1;
        const int c0 = (tid & 1) * 32;
        const int grow = row0 + r;
#pragma unroll
        for (int j = 0; j < 8; j++) {
            float4 v = make_float4(0.f, 0.f, 0.f, 0.f);
            if (grow < n_nodes)
                v = *reinterpret_cast<const float4*>(X + grow * D + c0 + j * 4);
            *reinterpret_cast<__half2*>(&sA[r][c0 + j * 4])     = __floats2half2_rn(v.x, v.y);
            *reinterpret_cast<__half2*>(&sA[r][c0 + j * 4 + 2]) = __floats2half2_rn(v.z, v.w);
        }
    }
    __syncthreads();

    const int mr = warp * 16;
    const int a_row = mr + (lane & 7) + ((lane & 8) ? 8 : 0);
    const int a_col = (lane & 16) ? 8 : 0;
    const int b_row = (lane & 15);

    float acc[8][4] = {};

#pragma unroll
    for (int ks = 0; ks < 4; ks++) {
        const int k0 = ks * 16;
        uint32_t a0, a1, a2, a3;
        ldsm_x4(a0, a1, a2, a3, smem_u32(&sA[a_row][k0 + a_col]));
#pragma unroll
        for (int n = 0; n < 8; n++) {
            uint32_t b0, b1;
            ldsm_x2_trans(b0, b1, smem_u32(&sB[k0 + b_row][n * 8]));
            mma_16816(acc[n], a0, a1, a2, a3, b0, b1);
        }
    }

    // epilogue
    const int g = lane >> 2;
    const int tg = lane & 3;
    const int r0g = row0 + mr + g;
    const int r1g = r0g + 8;
#pragma unroll
    for (int n = 0; n < 8; n++) {
        const int c = n * 8 + tg * 2;
        if (r0g < n_nodes)
            *reinterpret_cast<__half2*>(&g_support_h[r0g * D + c]) =
                __floats2half2_rn(acc[n][0], acc[n][1]);
        if (r1g < n_nodes)
            *reinterpret_cast<__half2*>(&g_support_h[r1g * D + c]) =
                __floats2half2_rn(acc[n][2], acc[n][3]);
    }
}

// ---------------------------------------------------------------------------
// gather: one warp per node; lane l owns features [2l, 2l+1] (one half2).
// 8x edge unroll for MLP. out[n] = b + sum_e w_e * support_h[src_e]
// ---------------------------------------------------------------------------
__global__ __launch_bounds__(256) void gather_kernel(
    const float* __restrict__ b, float* __restrict__ out, int n_nodes) {
    int warp = (blockIdx.x * blockDim.x + threadIdx.x) >> 5;
    int lane = threadIdx.x & 31;
    if (warp >= n_nodes) return;

    int deg = g_cnt[warp];
    bool ovfl = deg > CAP;
    if (ovfl) deg = CAP;
    const int2* row = &g_bucket[warp * CAP];

    float2 a0 = make_float2(0.f, 0.f), a1 = make_float2(0.f, 0.f);
    float2 a2 = make_float2(0.f, 0.f), a3 = make_float2(0.f, 0.f);

    const __half2* sup2 = reinterpret_cast<const __half2*>(g_support_h);

    for (int p = 0; p < deg; p += 32) {
        int m = deg - p; if (m > 32) m = 32;
        int2 ed = make_int2(0, 0);
        if (lane < m) ed = row[p + lane];
        int j = 0;
        for (; j + 8 <= m; j += 8) {
            int s[8]; float w[8];
#pragma unroll
            for (int q = 0; q < 8; q++) {
                s[q] = __shfl_sync(0xffffffffu, ed.x, j + q);
                w[q] = __int_as_float(__shfl_sync(0xffffffffu, ed.y, j + q));
            }
            float2 v[8];
#pragma unroll
            for (int q = 0; q < 8; q++)
                v[q] = __half22float2(sup2[s[q] * (D / 2) + lane]);
            a0.x += w[0] * v[0].x; a0.y += w[0] * v[0].y;
            a1.x += w[1] * v[1].x; a1.y += w[1] * v[1].y;
            a2.x += w[2] * v[2].x; a2.y += w[2] * v[2].y;
            a3.x += w[3] * v[3].x; a3.y += w[3] * v[3].y;
            a0.x += w[4] * v[4].x; a0.y += w[4] * v[4].y;
            a1.x += w[5] * v[5].x; a1.y += w[5] * v[5].y;
            a2.x += w[6] * v[6].x; a2.y += w[6] * v[6].y;
            a3.x += w[7] * v[7].x; a3.y += w[7] * v[7].y;
        }
        for (; j < m; j++) {
            int s = __shfl_sync(0xffffffffu, ed.x, j);
            float wv = __int_as_float(__shfl_sync(0xffffffffu, ed.y, j));
            float2 v = __half22float2(sup2[s * (D / 2) + lane]);
            a0.x += wv * v.x; a0.y += wv * v.y;
        }
    }

    if (ovfl) {
        int novf = g_cnt[MAX_NODES];
        if (novf > OVF_CAP) novf = OVF_CAP;
        for (int o = 0; o < novf; o++) {
            int3 ed = g_ovf[o];
            if (ed.x == warp) {
                float wv = __int_as_float(ed.z);
                float2 v = __half22float2(sup2[ed.y * (D / 2) + lane]);
                a0.x += wv * v.x; a0.y += wv * v.y;
            }
        }
    }

    float2 bb = reinterpret_cast<const float2*>(b)[lane];
    float2 r;
    r.x = (a0.x + a1.x) + (a2.x + a3.x) + bb.x;
    r.y = (a0.y + a1.y) + (a2.y + a3.y) + bb.y;
    reinterpret_cast<float2*>(out + warp * D)[lane] = r;
}

// ---------------------------------------------------------------------------
extern "C" void kernel_launch(void* const* d_in, const int* in_sizes, int n_in,
                              void* d_out, int out_size) {
    const float* X    = (const float*)d_in[0];
    const int*   esrc = (const int*)d_in[1];
    const int*   edst = (const int*)d_in[2];
    const float* ew   = (const float*)d_in[3];
    const float* W    = (const float*)d_in[4];
    const float* b    = (const float*)d_in[5];
    float*       out  = (float*)d_out;

    int n_nodes = in_sizes[0] / D;
    int n_edges = in_sizes[1];

    static cudaStream_t s_side = nullptr;
    static cudaEvent_t s_fork = nullptr, s_join = nullptr;
    if (!s_side) {
        cudaStreamCreateWithFlags(&s_side, cudaStreamNonBlocking);
        cudaEventCreateWithFlags(&s_fork, cudaEventDisableTiming);
        cudaEventCreateWithFlags(&s_join, cudaEventDisableTiming);
    }

    // fork: GEMM concurrent with bucket build
    cudaEventRecord(s_fork, 0);
    cudaStreamWaitEvent(s_side, s_fork, 0);
    gcn_gemm_hmma<<<(n_nodes + GR - 1) / GR, 128, 0, s_side>>>(X, W, n_nodes);
    cudaEventRecord(s_join, s_side);

    // bucket build on main stream (single memset covers counters + ovf count)
    void* p_cnt = nullptr;
    cudaGetSymbolAddress(&p_cnt, g_cnt);
    cudaMemsetAsync(p_cnt, 0, (MAX_NODES + 1) * sizeof(int));
    fill_kernel<<<(n_edges + 255) / 256, 256>>>(esrc, edst, ew, n_edges);

    // join: gather needs buckets + support
    cudaStreamWaitEvent(0, s_join, 0);
    gather_kernel<<<(n_nodes * 32 + 255) / 256, 256>>>(b, out, n_nodes);
}

// round 11
// speedup vs baseline: 1.0403x; 1.0403x over previous
#include <cuda_runtime.h>
#include <cuda_fp16.h>
#include <cstdint>

#define D 64
#define MAX_NODES 50000
#define CAP 128            // bucket capacity per node (Poisson(16) degrees)
#define OVF_CAP 4096

// ---- scratch (zero-initialized at load; kernels restore zeros each run) ----
__device__ __half g_support_h[MAX_NODES * D];       // X @ W in fp16 (6.4 MB)
__device__ int    g_cnt[MAX_NODES + 1];             // per-dst counters; [MAX_NODES] = novf
__device__ int2   g_bucket[MAX_NODES * CAP];        // (src, bitcast(w)) per dst (51.2 MB)
__device__ int3   g_ovf[OVF_CAP];                   // (dst, src, w) spill

// ---------------------------------------------------------------------------
// single-pass bucket fill, 2 edges per thread
// ---------------------------------------------------------------------------
__device__ __forceinline__ void fill_one(int d, int s, float w) {
    int slot = atomicAdd(&g_cnt[d], 1);
    if (slot < CAP) {
        g_bucket[d * CAP + slot] = make_int2(s, __float_as_int(w));
    } else {
        int o = atomicAdd(&g_cnt[MAX_NODES], 1);
        if (o < OVF_CAP)
            g_ovf[o] = make_int3(d, s, __float_as_int(w));
    }
}

__global__ void fill_kernel(const int* __restrict__ edge_src,
                            const int* __restrict__ edge_dst,
                            const float* __restrict__ edge_weight, int n_edges) {
    int t = blockIdx.x * blockDim.x + threadIdx.x;
    int e = t * 2;
    if (e + 1 < n_edges) {
        int2 d = *reinterpret_cast<const int2*>(edge_dst + e);
        int2 s = *reinterpret_cast<const int2*>(edge_src + e);
        float2 w = *reinterpret_cast<const float2*>(edge_weight + e);
        fill_one(d.x, s.x, w.x);
        fill_one(d.y, s.y, w.y);
    } else if (e < n_edges) {
        fill_one(edge_dst[e], edge_src[e], edge_weight[e]);
    }
}

// ---------------------------------------------------------------------------
// tensor-core GEMM (R9 config, measured 11.6us): support_h = fp16(X @ W).
// Block = 128 rows x 64 cols, 256 threads (8 warps), warp = 16-row strip.
// ---------------------------------------------------------------------------
#define GR 128
#define LDA 72   // padded leading dim in halves (144B rows -> conflict-free ldmatrix)

__device__ __forceinline__ uint32_t smem_u32(const void* p) {
    return static_cast<uint32_t>(__cvta_generic_to_shared(p));
}

__device__ __forceinline__ void ldsm_x4(uint32_t& r0, uint32_t& r1,
                                        uint32_t& r2, uint32_t& r3, uint32_t addr) {
    asm volatile("ldmatrix.sync.aligned.m8n8.x4.shared.b16 {%0,%1,%2,%3}, [%4];"
                 : "=r"(r0), "=r"(r1), "=r"(r2), "=r"(r3) : "r"(addr));
}

__device__ __forceinline__ void ldsm_x2_trans(uint32_t& r0, uint32_t& r1, uint32_t addr) {
    asm volatile("ldmatrix.sync.aligned.m8n8.x2.trans.shared.b16 {%0,%1}, [%2];"
                 : "=r"(r0), "=r"(r1) : "r"(addr));
}

__device__ __forceinline__ void mma_16816(float* c, uint32_t a0, uint32_t a1,
                                          uint32_t a2, uint32_t a3,
                                          uint32_t b0, uint32_t b1) {
    asm volatile(
        "mma.sync.aligned.m16n8k16.row.col.f32.f16.f16.f32 "
        "{%0,%1,%2,%3}, {%4,%5,%6,%7}, {%8,%9}, {%0,%1,%2,%3};"
        : "+f"(c[0]), "+f"(c[1]), "+f"(c[2]), "+f"(c[3])
        : "r"(a0), "r"(a1), "r"(a2), "r"(a3), "r"(b0), "r"(b1));
}

__global__ __launch_bounds__(256) void gcn_gemm_hmma(
    const float* __restrict__ X, const float* __restrict__ W, int n_nodes) {
    __shared__ __align__(16) __half sA[GR][LDA];  // X tile fp16 (18 KB)
    __shared__ __align__(16) __half sB[D][LDA];   // W fp16      (9 KB)

    const int tid = threadIdx.x;
    const int lane = tid & 31;
    const int warp = tid >> 5;
    const int row0 = blockIdx.x * GR;

    // load + convert W (64x64): thread t -> row t>>2, cols (t&3)*16..+15
    {
        const int r = tid >> 2;
        const int c0 = (tid & 3) * 16;
#pragma unroll
        for (int j = 0; j < 4; j++) {
            float4 v = *reinterpret_cast<const float4*>(W + r * D + c0 + j * 4);
            *reinterpret_cast<__half2*>(&sB[r][c0 + j * 4])     = __floats2half2_rn(v.x, v.y);
            *reinterpret_cast<__half2*>(&sB[r][c0 + j * 4 + 2]) = __floats2half2_rn(v.z, v.w);
        }
    }
    // load + convert X tile (128x64): thread t -> row t>>1, half (t&1)*32
    {
        const int r = tid >> 1;
        const int c0 = (tid & 1) * 32;
        const int grow = row0 + r;
#pragma unroll
        for (int j = 0; j < 8; j++) {
            float4 v = make_float4(0.f, 0.f, 0.f, 0.f);
            if (grow < n_nodes)
                v = *reinterpret_cast<const float4*>(X + grow * D + c0 + j * 4);
            *reinterpret_cast<__half2*>(&sA[r][c0 + j * 4])     = __floats2half2_rn(v.x, v.y);
            *reinterpret_cast<__half2*>(&sA[r][c0 + j * 4 + 2]) = __floats2half2_rn(v.z, v.w);
        }
    }
    __syncthreads();

    const int mr = warp * 16;
    const int a_row = mr + (lane & 7) + ((lane & 8) ? 8 : 0);
    const int a_col = (lane & 16) ? 8 : 0;
    const int b_row = (lane & 15);

    float acc[8][4] = {};

#pragma unroll
    for (int ks = 0; ks < 4; ks++) {
        const int k0 = ks * 16;
        uint32_t a0, a1, a2, a3;
        ldsm_x4(a0, a1, a2, a3, smem_u32(&sA[a_row][k0 + a_col]));
#pragma unroll
        for (int n = 0; n < 8; n++) {
            uint32_t b0, b1;
            ldsm_x2_trans(b0, b1, smem_u32(&sB[k0 + b_row][n * 8]));
            mma_16816(acc[n], a0, a1, a2, a3, b0, b1);
        }
    }

    const int g = lane >> 2;
    const int tg = lane & 3;
    const int r0g = row0 + mr + g;
    const int r1g = r0g + 8;
#pragma unroll
    for (int n = 0; n < 8; n++) {
        const int c = n * 8 + tg * 2;
        if (r0g < n_nodes)
            *reinterpret_cast<__half2*>(&g_support_h[r0g * D + c]) =
                __floats2half2_rn(acc[n][0], acc[n][1]);
        if (r1g < n_nodes)
            *reinterpret_cast<__half2*>(&g_support_h[r1g * D + c]) =
                __floats2half2_rn(acc[n][2], acc[n][3]);
    }
}

// ---------------------------------------------------------------------------
// gather: one warp per node; lane l owns features [2l, 2l+1] (one half2).
// Self-cleaning: zeroes g_cnt for the next graph replay.
// ---------------------------------------------------------------------------
__global__ __launch_bounds__(256) void gather_kernel(
    const float* __restrict__ b, float* __restrict__ out, int n_nodes) {
    int warp = (blockIdx.x * blockDim.x + threadIdx.x) >> 5;
    int lane = threadIdx.x & 31;
    if (warp >= n_nodes) return;

    int deg = g_cnt[warp];
    bool ovfl = deg > CAP;
    if (ovfl) deg = CAP;
    const int2* row = &g_bucket[warp * CAP];

    float2 a0 = make_float2(0.f, 0.f), a1 = make_float2(0.f, 0.f);
    float2 a2 = make_float2(0.f, 0.f), a3 = make_float2(0.f, 0.f);

    const __half2* sup2 = reinterpret_cast<const __half2*>(g_support_h);

    for (int p = 0; p < deg; p += 32) {
        int m = deg - p; if (m > 32) m = 32;
        int2 ed = make_int2(0, 0);
        if (lane < m) ed = row[p + lane];
        int j = 0;
        for (; j + 8 <= m; j += 8) {
            int s[8]; float w[8];
#pragma unroll
            for (int q = 0; q < 8; q++) {
                s[q] = __shfl_sync(0xffffffffu, ed.x, j + q);
                w[q] = __int_as_float(__shfl_sync(0xffffffffu, ed.y, j + q));
            }
            float2 v[8];
#pragma unroll
            for (int q = 0; q < 8; q++)
                v[q] = __half22float2(sup2[s[q] * (D / 2) + lane]);
            a0.x += w[0] * v[0].x; a0.y += w[0] * v[0].y;
            a1.x += w[1] * v[1].x; a1.y += w[1] * v[1].y;
            a2.x += w[2] * v[2].x; a2.y += w[2] * v[2].y;
            a3.x += w[3] * v[3].x; a3.y += w[3] * v[3].y;
            a0.x += w[4] * v[4].x; a0.y += w[4] * v[4].y;
            a1.x += w[5] * v[5].x; a1.y += w[5] * v[5].y;
            a2.x += w[6] * v[6].x; a2.y += w[6] * v[6].y;
            a3.x += w[7] * v[7].x; a3.y += w[7] * v[7].y;
        }
        for (; j < m; j++) {
            int s = __shfl_sync(0xffffffffu, ed.x, j);
            float wv = __int_as_float(__shfl_sync(0xffffffffu, ed.y, j));
            float2 v = __half22float2(sup2[s * (D / 2) + lane]);
            a0.x += wv * v.x; a0.y += wv * v.y;
        }
    }

    if (ovfl) {
        int novf = g_cnt[MAX_NODES];
        if (novf > OVF_CAP) novf = OVF_CAP;
        for (int o = 0; o < novf; o++) {
            int3 ed = g_ovf[o];
            if (ed.x == warp) {
                float wv = __int_as_float(ed.z);
                float2 v = __half22float2(sup2[ed.y * (D / 2) + lane]);
                a0.x += wv * v.x; a0.y += wv * v.y;
            }
        }
    }

    // self-clean for the next replay (replaces the memset node)
    if (lane == 0) g_cnt[warp] = 0;
    if (warp == 0 && lane == 1) g_cnt[MAX_NODES] = 0;

    float2 bb = reinterpret_cast<const float2*>(b)[lane];
    float2 r;
    r.x = (a0.x + a1.x) + (a2.x + a3.x) + bb.x;
    r.y = (a0.y + a1.y) + (a2.y + a3.y) + bb.y;
    reinterpret_cast<float2*>(out + warp * D)[lane] = r;
}

// ---------------------------------------------------------------------------
extern "C" void kernel_launch(void* const* d_in, const int* in_sizes, int n_in,
                              void* d_out, int out_size) {
    const float* X    = (const float*)d_in[0];
    const int*   esrc = (const int*)d_in[1];
    const int*   edst = (const int*)d_in[2];
    const float* ew   = (const float*)d_in[3];
    const float* W    = (const float*)d_in[4];
    const float* b    = (const float*)d_in[5];
    float*       out  = (float*)d_out;

    int n_nodes = in_sizes[0] / D;
    int n_edges = in_sizes[1];

    static cudaStream_t s_side = nullptr;
    static cudaEvent_t s_fork = nullptr, s_join = nullptr;
    if (!s_side) {
        cudaStreamCreateWithFlags(&s_side, cudaStreamNonBlocking);
        cudaEventCreateWithFlags(&s_fork, cudaEventDisableTiming);
        cudaEventCreateWithFlags(&s_join, cudaEventDisableTiming);
    }

    // fork: GEMM concurrent with bucket build
    cudaEventRecord(s_fork, 0);
    cudaStreamWaitEvent(s_side, s_fork, 0);
    gcn_gemm_hmma<<<(n_nodes + GR - 1) / GR, 256, 0, s_side>>>(X, W, n_nodes);
    cudaEventRecord(s_join, s_side);

    // bucket build on main stream (counters are pre-zeroed; gather re-zeroes)
    fill_kernel<<<(n_edges / 2 + 255) / 256, 256>>>(esrc, edst, ew, n_edges);

    // join: gather needs buckets + support
    cudaStreamWaitEvent(0, s_join, 0);
    gather_kernel<<<(n_nodes * 32 + 255) / 256, 256>>>(b, out, n_nodes);
}

// round 12
// speedup vs baseline: 1.1046x; 1.0618x over previous
#include <cuda_runtime.h>
#include <cuda_fp16.h>
#include <cstdint>

#define D 64
#define MAX_NODES 50000
#define CAP 128            // bucket capacity per node (Poisson(16) degrees)
#define OVF_CAP 4096
#define FILL_BLOCKS 148

// ---- scratch (zero-initialized at load; gather restores zeros each run) ----
__device__ __half   g_support_h[MAX_NODES * D];     // X @ W in fp16 (6.4 MB)
__device__ int      g_cnt[MAX_NODES + 1];           // per-dst counters; [MAX_NODES] = novf
__device__ unsigned g_bucket[MAX_NODES * CAP];      // (fp16 w << 16 | src) per dst (25.6 MB)
__device__ int3     g_ovf[OVF_CAP];                 // (dst, src, fp32 w) spill

// ---------------------------------------------------------------------------
__device__ __forceinline__ void fill_one(int d, int s, float w) {
    int slot = atomicAdd(&g_cnt[d], 1);
    if (slot < CAP) {
        unsigned pk = (unsigned)s |
                      ((unsigned)__half_as_ushort(__float2half_rn(w)) << 16);
        g_bucket[d * CAP + slot] = pk;
    } else {
        int o = atomicAdd(&g_cnt[MAX_NODES], 1);
        if (o < OVF_CAP)
            g_ovf[o] = make_int3(d, s, __float_as_int(w));
    }
}

// ---------------------------------------------------------------------------
// fused: blocks [0, gemm_blocks)  -> HMMA GEMM (support_h = fp16(X @ W))
//        blocks [gemm_blocks, +FILL_BLOCKS) -> bucket fill (grid-stride)
// one co-resident wave => true overlap, no streams/events needed.
// ---------------------------------------------------------------------------
#define GR 128
#define LDA 72   // padded leading dim in halves -> conflict-free ldmatrix

__device__ __forceinline__ uint32_t smem_u32(const void* p) {
    return static_cast<uint32_t>(__cvta_generic_to_shared(p));
}

__device__ __forceinline__ void ldsm_x4(uint32_t& r0, uint32_t& r1,
                                        uint32_t& r2, uint32_t& r3, uint32_t addr) {
    asm volatile("ldmatrix.sync.aligned.m8n8.x4.shared.b16 {%0,%1,%2,%3}, [%4];"
                 : "=r"(r0), "=r"(r1), "=r"(r2), "=r"(r3) : "r"(addr));
}

__device__ __forceinline__ void ldsm_x2_trans(uint32_t& r0, uint32_t& r1, uint32_t addr) {
    asm volatile("ldmatrix.sync.aligned.m8n8.x2.trans.shared.b16 {%0,%1}, [%2];"
                 : "=r"(r0), "=r"(r1) : "r"(addr));
}

__device__ __forceinline__ void mma_16816(float* c, uint32_t a0, uint32_t a1,
                                          uint32_t a2, uint32_t a3,
                                          uint32_t b0, uint32_t b1) {
    asm volatile(
        "mma.sync.aligned.m16n8k16.row.col.f32.f16.f16.f32 "
        "{%0,%1,%2,%3}, {%4,%5,%6,%7}, {%8,%9}, {%0,%1,%2,%3};"
        : "+f"(c[0]), "+f"(c[1]), "+f"(c[2]), "+f"(c[3])
        : "r"(a0), "r"(a1), "r"(a2), "r"(a3), "r"(b0), "r"(b1));
}

__global__ __launch_bounds__(256) void fused_gemm_fill(
    const float* __restrict__ X, const float* __restrict__ W, int n_nodes,
    const int* __restrict__ edge_src, const int* __restrict__ edge_dst,
    const float* __restrict__ edge_weight, int n_edges, int gemm_blocks) {

    if (blockIdx.x >= gemm_blocks) {
        // ---- fill branch: 2 edges per iteration, grid-stride ----
        const int tid0 = (blockIdx.x - gemm_blocks) * blockDim.x + threadIdx.x;
        const int nthr = FILL_BLOCKS * blockDim.x;
        const int half = n_edges >> 1;
        for (int e2 = tid0; e2 < half; e2 += nthr) {
            const int e = e2 * 2;
            int2 d = *reinterpret_cast<const int2*>(edge_dst + e);
            int2 s = *reinterpret_cast<const int2*>(edge_src + e);
            float2 w = *reinterpret_cast<const float2*>(edge_weight + e);
            fill_one(d.x, s.x, w.x);
            fill_one(d.y, s.y, w.y);
        }
        if (tid0 == 0 && (n_edges & 1)) {
            const int e = n_edges - 1;
            fill_one(edge_dst[e], edge_src[e], edge_weight[e]);
        }
        return;
    }

    // ---- GEMM branch (R9/R11 config, measured 11.6-11.9us) ----
    __shared__ __align__(16) __half sA[GR][LDA];  // X tile fp16 (18 KB)
    __shared__ __align__(16) __half sB[D][LDA];   // W fp16      (9 KB)

    const int tid = threadIdx.x;
    const int lane = tid & 31;
    const int warp = tid >> 5;
    const int row0 = blockIdx.x * GR;

    {
        const int r = tid >> 2;
        const int c0 = (tid & 3) * 16;
#pragma unroll
        for (int j = 0; j < 4; j++) {
            float4 v = *reinterpret_cast<const float4*>(W + r * D + c0 + j * 4);
            *reinterpret_cast<__half2*>(&sB[r][c0 + j * 4])     = __floats2half2_rn(v.x, v.y);
            *reinterpret_cast<__half2*>(&sB[r][c0 + j * 4 + 2]) = __floats2half2_rn(v.z, v.w);
        }
    }
    {
        const int r = tid >> 1;
        const int c0 = (tid & 1) * 32;
        const int grow = row0 + r;
#pragma unroll
        for (int j = 0; j < 8; j++) {
            float4 v = make_float4(0.f, 0.f, 0.f, 0.f);
            if (grow < n_nodes)
                v = *reinterpret_cast<const float4*>(X + grow * D + c0 + j * 4);
            *reinterpret_cast<__half2*>(&sA[r][c0 + j * 4])     = __floats2half2_rn(v.x, v.y);
            *reinterpret_cast<__half2*>(&sA[r][c0 + j * 4 + 2]) = __floats2half2_rn(v.z, v.w);
        }
    }
    __syncthreads();

    const int mr = warp * 16;
    const int a_row = mr + (lane & 7) + ((lane & 8) ? 8 : 0);
    const int a_col = (lane & 16) ? 8 : 0;
    const int b_row = (lane & 15);

    float acc[8][4] = {};

#pragma unroll
    for (int ks = 0; ks < 4; ks++) {
        const int k0 = ks * 16;
        uint32_t a0, a1, a2, a3;
        ldsm_x4(a0, a1, a2, a3, smem_u32(&sA[a_row][k0 + a_col]));
#pragma unroll
        for (int n = 0; n < 8; n++) {
            uint32_t b0, b1;
            ldsm_x2_trans(b0, b1, smem_u32(&sB[k0 + b_row][n * 8]));
            mma_16816(acc[n], a0, a1, a2, a3, b0, b1);
        }
    }

    const int g = lane >> 2;
    const int tg = lane & 3;
    const int r0g = row0 + mr + g;
    const int r1g = r0g + 8;
#pragma unroll
    for (int n = 0; n < 8; n++) {
        const int c = n * 8 + tg * 2;
        if (r0g < n_nodes)
            *reinterpret_cast<__half2*>(&g_support_h[r0g * D + c]) =
                __floats2half2_rn(acc[n][0], acc[n][1]);
        if (r1g < n_nodes)
            *reinterpret_cast<__half2*>(&g_support_h[r1g * D + c]) =
                __floats2half2_rn(acc[n][2], acc[n][3]);
    }
}

// ---------------------------------------------------------------------------
// gather: one warp per node; lane l owns features [2l, 2l+1] (one half2).
// 4B packed edges: 1 shfl per edge. Self-cleaning counters.
// ---------------------------------------------------------------------------
__global__ __launch_bounds__(256) void gather_kernel(
    const float* __restrict__ b, float* __restrict__ out, int n_nodes) {
    int warp = (blockIdx.x * blockDim.x + threadIdx.x) >> 5;
    int lane = threadIdx.x & 31;
    if (warp >= n_nodes) return;

    int deg = g_cnt[warp];
    bool ovfl = deg > CAP;
    if (ovfl) deg = CAP;
    const unsigned* row = &g_bucket[warp * CAP];

    float2 a0 = make_float2(0.f, 0.f), a1 = make_float2(0.f, 0.f);
    float2 a2 = make_float2(0.f, 0.f), a3 = make_float2(0.f, 0.f);

    const __half2* sup2 = reinterpret_cast<const __half2*>(g_support_h);

    for (int p = 0; p < deg; p += 32) {
        int m = deg - p; if (m > 32) m = 32;
        unsigned ed = 0;
        if (lane < m) ed = row[p + lane];
        int j = 0;
        for (; j + 8 <= m; j += 8) {
            unsigned pk[8];
#pragma unroll
            for (int q = 0; q < 8; q++)
                pk[q] = __shfl_sync(0xffffffffu, ed, j + q);
            float2 v[8]; float w[8];
#pragma unroll
            for (int q = 0; q < 8; q++) {
                v[q] = __half22float2(sup2[(pk[q] & 0xFFFFu) * (D / 2) + lane]);
                w[q] = __half2float(__ushort_as_half((unsigned short)(pk[q] >> 16)));
            }
            a0.x += w[0] * v[0].x; a0.y += w[0] * v[0].y;
            a1.x += w[1] * v[1].x; a1.y += w[1] * v[1].y;
            a2.x += w[2] * v[2].x; a2.y += w[2] * v[2].y;
            a3.x += w[3] * v[3].x; a3.y += w[3] * v[3].y;
            a0.x += w[4] * v[4].x; a0.y += w[4] * v[4].y;
            a1.x += w[5] * v[5].x; a1.y += w[5] * v[5].y;
            a2.x += w[6] * v[6].x; a2.y += w[6] * v[6].y;
            a3.x += w[7] * v[7].x; a3.y += w[7] * v[7].y;
        }
        for (; j < m; j++) {
            unsigned pk = __shfl_sync(0xffffffffu, ed, j);
            float wv = __half2float(__ushort_as_half((unsigned short)(pk >> 16)));
            float2 v = __half22float2(sup2[(pk & 0xFFFFu) * (D / 2) + lane]);
            a0.x += wv * v.x; a0.y += wv * v.y;
        }
    }

    if (ovfl) {
        int novf = g_cnt[MAX_NODES];
        if (novf > OVF_CAP) novf = OVF_CAP;
        for (int o = 0; o < novf; o++) {
            int3 ed = g_ovf[o];
            if (ed.x == warp) {
                float wv = __int_as_float(ed.z);
                float2 v = __half22float2(sup2[ed.y * (D / 2) + lane]);
                a0.x += wv * v.x; a0.y += wv * v.y;
            }
        }
    }

    // self-clean for the next replay
    if (lane == 0) g_cnt[warp] = 0;
    if (warp == 0 && lane == 1) g_cnt[MAX_NODES] = 0;

    float2 bb = reinterpret_cast<const float2*>(b)[lane];
    float2 r;
    r.x = (a0.x + a1.x) + (a2.x + a3.x) + bb.x;
    r.y = (a0.y + a1.y) + (a2.y + a3.y) + bb.y;
    reinterpret_cast<float2*>(out + warp * D)[lane] = r;
}

// ---------------------------------------------------------------------------
extern "C" void kernel_launch(void* const* d_in, const int* in_sizes, int n_in,
                              void* d_out, int out_size) {
    const float* X    = (const float*)d_in[0];
    const int*   esrc = (const int*)d_in[1];
    const int*   edst = (const int*)d_in[2];
    const float* ew   = (const float*)d_in[3];
    const float* W    = (const float*)d_in[4];
    const float* b    = (const float*)d_in[5];
    float*       out  = (float*)d_out;

    int n_nodes = in_sizes[0] / D;
    int n_edges = in_sizes[1];
    int gemm_blocks = (n_nodes + GR - 1) / GR;

    fused_gemm_fill<<<gemm_blocks + FILL_BLOCKS, 256>>>(
        X, W, n_nodes, esrc, edst, ew, n_edges, gemm_blocks);
    gather_kernel<<<(n_nodes * 32 + 255) / 256, 256>>>(b, out, n_nodes);
}

// round 13
// speedup vs baseline: 1.1575x; 1.0478x over previous
#include <cuda_runtime.h>
#include <cuda_fp16.h>
#include <cstdint>

#define D 64
#define MAX_NODES 50000
#define CAP 128            // bucket capacity per node (Poisson(16) degrees)
#define OVF_CAP 4096
#define FILL_BLOCKS 148

// ---- scratch (zero-initialized at load; gather restores zeros each run) ----
__device__ __half   g_support_h[MAX_NODES * D];     // X @ W in fp16 (6.4 MB)
__device__ int      g_cnt[MAX_NODES + 1];           // per-dst counters; [MAX_NODES] = novf
__device__ unsigned g_bucket[MAX_NODES * CAP];      // (fp16 w << 16 | src) per dst (25.6 MB)
__device__ int3     g_ovf[OVF_CAP];                 // (dst, src, fp32 w) spill

// ---------------------------------------------------------------------------
__device__ __forceinline__ void fill_one(int d, int s, float w) {
    int slot = atomicAdd(&g_cnt[d], 1);
    if (slot < CAP) {
        unsigned pk = (unsigned)s |
                      ((unsigned)__half_as_ushort(__float2half_rn(w)) << 16);
        g_bucket[d * CAP + slot] = pk;
    } else {
        int o = atomicAdd(&g_cnt[MAX_NODES], 1);
        if (o < OVF_CAP)
            g_ovf[o] = make_int3(d, s, __float_as_int(w));
    }
}

// ---------------------------------------------------------------------------
// fused: blocks [0, gemm_blocks)  -> HMMA GEMM (support_h = fp16(X @ W))
//        blocks [gemm_blocks, +FILL_BLOCKS) -> bucket fill (grid-stride)
// ---------------------------------------------------------------------------
#define GR 128
#define LDA 72

__device__ __forceinline__ uint32_t smem_u32(const void* p) {
    return static_cast<uint32_t>(__cvta_generic_to_shared(p));
}

__device__ __forceinline__ void ldsm_x4(uint32_t& r0, uint32_t& r1,
                                        uint32_t& r2, uint32_t& r3, uint32_t addr) {
    asm volatile("ldmatrix.sync.aligned.m8n8.x4.shared.b16 {%0,%1,%2,%3}, [%4];"
                 : "=r"(r0), "=r"(r1), "=r"(r2), "=r"(r3) : "r"(addr));
}

__device__ __forceinline__ void ldsm_x2_trans(uint32_t& r0, uint32_t& r1, uint32_t addr) {
    asm volatile("ldmatrix.sync.aligned.m8n8.x2.trans.shared.b16 {%0,%1}, [%2];"
                 : "=r"(r0), "=r"(r1) : "r"(addr));
}

__device__ __forceinline__ void mma_16816(float* c, uint32_t a0, uint32_t a1,
                                          uint32_t a2, uint32_t a3,
                                          uint32_t b0, uint32_t b1) {
    asm volatile(
        "mma.sync.aligned.m16n8k16.row.col.f32.f16.f16.f32 "
        "{%0,%1,%2,%3}, {%4,%5,%6,%7}, {%8,%9}, {%0,%1,%2,%3};"
        : "+f"(c[0]), "+f"(c[1]), "+f"(c[2]), "+f"(c[3])
        : "r"(a0), "r"(a1), "r"(a2), "r"(a3), "r"(b0), "r"(b1));
}

__global__ __launch_bounds__(256) void fused_gemm_fill(
    const float* __restrict__ X, const float* __restrict__ W, int n_nodes,
    const int* __restrict__ edge_src, const int* __restrict__ edge_dst,
    const float* __restrict__ edge_weight, int n_edges, int gemm_blocks) {

    if (blockIdx.x >= gemm_blocks) {
        const int tid0 = (blockIdx.x - gemm_blocks) * blockDim.x + threadIdx.x;
        const int nthr = FILL_BLOCKS * blockDim.x;
        const int half = n_edges >> 1;
        for (int e2 = tid0; e2 < half; e2 += nthr) {
            const int e = e2 * 2;
            int2 d = *reinterpret_cast<const int2*>(edge_dst + e);
            int2 s = *reinterpret_cast<const int2*>(edge_src + e);
            float2 w = *reinterpret_cast<const float2*>(edge_weight + e);
            fill_one(d.x, s.x, w.x);
            fill_one(d.y, s.y, w.y);
        }
        if (tid0 == 0 && (n_edges & 1)) {
            const int e = n_edges - 1;
            fill_one(edge_dst[e], edge_src[e], edge_weight[e]);
        }
        return;
    }

    __shared__ __align__(16) __half sA[GR][LDA];
    __shared__ __align__(16) __half sB[D][LDA];

    const int tid = threadIdx.x;
    const int lane = tid & 31;
    const int warp = tid >> 5;
    const int row0 = blockIdx.x * GR;

    {
        const int r = tid >> 2;
        const int c0 = (tid & 3) * 16;
#pragma unroll
        for (int j = 0; j < 4; j++) {
            float4 v = *reinterpret_cast<const float4*>(W + r * D + c0 + j * 4);
            *reinterpret_cast<__half2*>(&sB[r][c0 + j * 4])     = __floats2half2_rn(v.x, v.y);
            *reinterpret_cast<__half2*>(&sB[r][c0 + j * 4 + 2]) = __floats2half2_rn(v.z, v.w);
        }
    }
    {
        const int r = tid >> 1;
        const int c0 = (tid & 1) * 32;
        const int grow = row0 + r;
#pragma unroll
        for (int j = 0; j < 8; j++) {
            float4 v = make_float4(0.f, 0.f, 0.f, 0.f);
            if (grow < n_nodes)
                v = *reinterpret_cast<const float4*>(X + grow * D + c0 + j * 4);
            *reinterpret_cast<__half2*>(&sA[r][c0 + j * 4])     = __floats2half2_rn(v.x, v.y);
            *reinterpret_cast<__half2*>(&sA[r][c0 + j * 4 + 2]) = __floats2half2_rn(v.z, v.w);
        }
    }
    __syncthreads();

    const int mr = warp * 16;
    const int a_row = mr + (lane & 7) + ((lane & 8) ? 8 : 0);
    const int a_col = (lane & 16) ? 8 : 0;
    const int b_row = (lane & 15);

    float acc[8][4] = {};

#pragma unroll
    for (int ks = 0; ks < 4; ks++) {
        const int k0 = ks * 16;
        uint32_t a0, a1, a2, a3;
        ldsm_x4(a0, a1, a2, a3, smem_u32(&sA[a_row][k0 + a_col]));
#pragma unroll
        for (int n = 0; n < 8; n++) {
            uint32_t b0, b1;
            ldsm_x2_trans(b0, b1, smem_u32(&sB[k0 + b_row][n * 8]));
            mma_16816(acc[n], a0, a1, a2, a3, b0, b1);
        }
    }

    const int g = lane >> 2;
    const int tg = lane & 3;
    const int r0g = row0 + mr + g;
    const int r1g = r0g + 8;
#pragma unroll
    for (int n = 0; n < 8; n++) {
        const int c = n * 8 + tg * 2;
        if (r0g < n_nodes)
            *reinterpret_cast<__half2*>(&g_support_h[r0g * D + c]) =
                __floats2half2_rn(acc[n][0], acc[n][1]);
        if (r1g < n_nodes)
            *reinterpret_cast<__half2*>(&g_support_h[r1g * D + c]) =
                __floats2half2_rn(acc[n][2], acc[n][3]);
    }
}

// ---------------------------------------------------------------------------
// gather: one warp per node, TWO edges in flight per warp.
// Lanes 0-15 take even edges, 16-31 take odd edges; each lane owns 4 features
// (one uint2 = 2x half2 load). One shfl feeds both halves (per-half src idx).
// Epilogue merges halves with 4 shfl_down(16); lanes 0-15 add bias + store.
// ---------------------------------------------------------------------------
__global__ __launch_bounds__(256) void gather_kernel(
    const float* __restrict__ b, float* __restrict__ out, int n_nodes) {
    int warp = (blockIdx.x * blockDim.x + threadIdx.x) >> 5;
    int lane = threadIdx.x & 31;
    if (warp >= n_nodes) return;

    const int hw = lane >> 4;        // which half-warp (edge parity)
    const int l16 = lane & 15;       // feature group: owns features [4*l16, +4)

    int deg = g_cnt[warp];
    bool ovfl = deg > CAP;
    if (ovfl) deg = CAP;
    const unsigned* row = &g_bucket[warp * CAP];

    float4 acc = make_float4(0.f, 0.f, 0.f, 0.f);
    const __half* sup = g_support_h;

    for (int p = 0; p < deg; p += 32) {
        int m = deg - p; if (m > 32) m = 32;
        unsigned ed = 0;
        if (lane < m) ed = row[p + lane];
        int j = 0;
        // 8 edges per iteration (4 per half-warp)
        for (; j + 8 <= m; j += 8) {
            unsigned pk[4];
#pragma unroll
            for (int q = 0; q < 4; q++)
                pk[q] = __shfl_sync(0xffffffffu, ed, j + 2 * q + hw);
            uint2 hv[4];
#pragma unroll
            for (int q = 0; q < 4; q++)
                hv[q] = *reinterpret_cast<const uint2*>(
                    sup + (pk[q] & 0xFFFFu) * D + l16 * 4);
#pragma unroll
            for (int q = 0; q < 4; q++) {
                float w = __half2float(__ushort_as_half((unsigned short)(pk[q] >> 16)));
                float2 v01 = __half22float2(*reinterpret_cast<__half2*>(&hv[q].x));
                float2 v23 = __half22float2(*reinterpret_cast<__half2*>(&hv[q].y));
                acc.x += w * v01.x; acc.y += w * v01.y;
                acc.z += w * v23.x; acc.w += w * v23.y;
            }
        }
        // tail: 2 edges per step; lanes whose ed slot >= m carry w=0 (padding)
        for (; j < m; j += 2) {
            int idx = j + hw;                       // <= 31 always (m <= 32)
            unsigned pk = __shfl_sync(0xffffffffu, ed, idx > 31 ? 31 : idx);
            if (idx >= m) pk = 0;                   // zero weight, src 0
            float w = __half2float(__ushort_as_half((unsigned short)(pk >> 16)));
            uint2 hv = *reinterpret_cast<const uint2*>(
                sup + (pk & 0xFFFFu) * D + l16 * 4);
            float2 v01 = __half22float2(*reinterpret_cast<__half2*>(&hv.x));
            float2 v23 = __half22float2(*reinterpret_cast<__half2*>(&hv.y));
            acc.x += w * v01.x; acc.y += w * v01.y;
            acc.z += w * v23.x; acc.w += w * v23.y;
        }
    }

    // merge the two half-warp accumulators onto lanes 0-15
    acc.x += __shfl_down_sync(0xffffffffu, acc.x, 16);
    acc.y += __shfl_down_sync(0xffffffffu, acc.y, 16);
    acc.z += __shfl_down_sync(0xffffffffu, acc.z, 16);
    acc.w += __shfl_down_sync(0xffffffffu, acc.w, 16);

    // overflow path (never taken for this dataset; correct for any input)
    if (ovfl && hw == 0) {
        int novf = g_cnt[MAX_NODES];
        if (novf > OVF_CAP) novf = OVF_CAP;
        for (int o = 0; o < novf; o++) {
            int3 ed = g_ovf[o];
            if (ed.x == warp) {
                float w = __int_as_float(ed.z);
                uint2 hv = *reinterpret_cast<const uint2*>(sup + ed.y * D + l16 * 4);
                float2 v01 = __half22float2(*reinterpret_cast<__half2*>(&hv.x));
                float2 v23 = __half22float2(*reinterpret_cast<__half2*>(&hv.y));
                acc.x += w * v01.x; acc.y += w * v01.y;
                acc.z += w * v23.x; acc.w += w * v23.y;
            }
        }
    }

    // self-clean for the next replay
    if (lane == 0) g_cnt[warp] = 0;
    if (warp == 0 && lane == 1) g_cnt[MAX_NODES] = 0;

    if (hw == 0) {
        float4 bb = reinterpret_cast<const float4*>(b)[l16];
        acc.x += bb.x; acc.y += bb.y; acc.z += bb.z; acc.w += bb.w;
        *reinterpret_cast<float4*>(out + warp * D + l16 * 4) = acc;
    }
}

// ---------------------------------------------------------------------------
extern "C" void kernel_launch(void* const* d_in, const int* in_sizes, int n_in,
                              void* d_out, int out_size) {
    const float* X    = (const float*)d_in[0];
    const int*   esrc = (const int*)d_in[1];
    const int*   edst = (const int*)d_in[2];
    const float* ew   = (const float*)d_in[3];
    const float* W    = (const float*)d_in[4];
    const float* b    = (const float*)d_in[5];
    float*       out  = (float*)d_out;

    int n_nodes = in_sizes[0] / D;
    int n_edges = in_sizes[1];
    int gemm_blocks = (n_nodes + GR - 1) / GR;

    fused_gemm_fill<<<gemm_blocks + FILL_BLOCKS, 256>>>(
        X, W, n_nodes, esrc, edst, ew, n_edges, gemm_blocks);
    gather_kernel<<<(n_nodes * 32 + 255) / 256, 256>>>(b, out, n_nodes);
}